// round 12
// baseline (speedup 1.0000x reference)
#include <cuda_runtime.h>
#include <cuda_fp16.h>
#include <cstdint>

// FlashAttentionScore B=2,N=16,S=2048,D=128 fp32 causal.
// prep: K,V -> fp16 fragment images (V transposed), strides 288/160.
// main: BM=128 (M_warp=32: K/V fragments reused across two rowblocks),
//       cp.async early-prefetch, mma.sync fp16 1-term QK and PV.
// out layout: [out 32*2048*128][max x8][sum x8]

#define S_LEN 2048
#define DH    128
#define BM    128
#define BN    64
#define NT    128
#define NHEAD 32
#define NTILE 32            // 64-key tiles per head
#define NQT   16            // 128-row q tiles

#define RS_QK 288           // 256B data + 32B pad (≡8 mod 32 words)
#define RS_V  160           // 128B data + 32B pad
#define K_IMG (64*RS_QK)    // 18432
#define V_IMG (128*RS_V)    // 20480

#define SM_Q  0             // 128*288 = 36864
#define SM_K  36864
#define SM_V  55296
#define SMEM_BYTES 75776    // 2 CTAs/SM

__device__ __align__(16) char g_kimg[NHEAD * NTILE * K_IMG];   // 18.9 MB
__device__ __align__(16) char g_vimg[NHEAD * NTILE * V_IMG];   // 21.0 MB

__device__ __forceinline__ float ex2f_(float x){
    float r; asm("ex2.approx.ftz.f32 %0, %1;" : "=f"(r) : "f"(x)); return r;
}
__device__ __forceinline__ uint32_t pkh(__half a, __half b){
    return (uint32_t)__half_as_ushort(a) | ((uint32_t)__half_as_ushort(b) << 16);
}
__device__ __forceinline__ void mma_f16(float c[4],
        uint32_t a0, uint32_t a1, uint32_t a2, uint32_t a3,
        uint32_t b0, uint32_t b1){
    asm volatile(
        "mma.sync.aligned.m16n8k16.row.col.f32.f16.f16.f32 "
        "{%0,%1,%2,%3}, {%4,%5,%6,%7}, {%8,%9}, {%0,%1,%2,%3};"
        : "+f"(c[0]), "+f"(c[1]), "+f"(c[2]), "+f"(c[3])
        : "r"(a0), "r"(a1), "r"(a2), "r"(a3), "r"(b0), "r"(b1));
}
__device__ __forceinline__ uint32_t smem_u32(const void* p){
    uint32_t a;
    asm("{ .reg .u64 t; cvta.to.shared.u64 t, %1; cvt.u32.u64 %0, t; }" : "=r"(a) : "l"(p));
    return a;
}
__device__ __forceinline__ void cpa16(uint32_t s, const char* g){
    asm volatile("cp.async.cg.shared.global [%0], [%1], 16;" :: "r"(s), "l"(g));
}
#define CPA_COMMIT() asm volatile("cp.async.commit_group;" ::: "memory")
#define CPA_WAIT(n)  asm volatile("cp.async.wait_group %0;" :: "n"(n) : "memory")

// Fragment image layout: addr(row,kk,c) = row*RS + kk*32 + c*8
//   8B unit = [pair(8kk+c), pair(8kk+4+c)], pair w = k-elements {2w, 2w+1}

// ---------------- prep (unchanged from R11) ----------------
__global__ void __launch_bounds__(NT)
fa_prep_kernel(const float* __restrict__ k, const float* __restrict__ v)
{
    const int t  = threadIdx.x;
    const int kt = blockIdx.x;
    const int h  = blockIdx.y;
    const int img = h * NTILE + kt;

    {
        const float* Kt = k + ((size_t)h * S_LEN + (size_t)kt * BN) * DH;
        char* kb = g_kimg + (size_t)img * K_IMG;
#pragma unroll
        for (int i = 0; i < 16; ++i){
            int idx = t + NT * i;
            int row = idx >> 5, kc = idx & 31;
            int kk = kc >> 2, c = kc & 3;
            int d0 = 16*kk + 2*c;
            float2 v0 = *(const float2*)(Kt + row * DH + d0);
            float2 v1 = *(const float2*)(Kt + row * DH + d0 + 8);
            uint2 u = make_uint2(pkh(__float2half_rn(v0.x), __float2half_rn(v0.y)),
                                 pkh(__float2half_rn(v1.x), __float2half_rn(v1.y)));
            *(uint2*)(kb + row * RS_QK + kk * 32 + c * 8) = u;
        }
    }
    {
        const float* Vt = v + ((size_t)h * S_LEN + (size_t)kt * BN) * DH;
        char* vb = g_vimg + (size_t)img * V_IMG;
        int m = t & 63, g = t >> 6;
#pragma unroll
        for (int i = 0; i < 8; ++i){
            int j  = 8 * g + i;
            int kk = j >> 2, c = j & 3;
            int k0 = 16*kk + 2*c;
            float2 va = *(const float2*)(Vt + (k0    ) * DH + 2*m);
            float2 vb2= *(const float2*)(Vt + (k0 + 1) * DH + 2*m);
            float2 vc = *(const float2*)(Vt + (k0 + 8) * DH + 2*m);
            float2 vd = *(const float2*)(Vt + (k0 + 9) * DH + 2*m);
            *(uint2*)(vb + (2*m)   * RS_V + kk * 32 + c * 8) =
                make_uint2(pkh(__float2half_rn(va.x), __float2half_rn(vb2.x)),
                           pkh(__float2half_rn(vc.x), __float2half_rn(vd.x)));
            *(uint2*)(vb + (2*m+1) * RS_V + kk * 32 + c * 8) =
                make_uint2(pkh(__float2half_rn(va.y), __float2half_rn(vb2.y)),
                           pkh(__float2half_rn(vc.y), __float2half_rn(vd.y)));
        }
    }
}

// ---------------- main ----------------
__global__ void __launch_bounds__(NT, 2)
fa_main_kernel(const float* __restrict__ q, float* __restrict__ out,
               float* __restrict__ omax, float* __restrict__ osum)
{
    extern __shared__ char sm[];
    const int t = threadIdx.x;
    const int l = t & 31;
    const int w = t >> 5;
    const int h = blockIdx.y;
    const int qt = NQT - 1 - (int)blockIdx.x;   // big tiles first
    const int nkt = 2 * qt + 2;

    const uint32_t sb = smem_u32(sm);
    const char* gk = g_kimg + (size_t)h * NTILE * K_IMG;
    const char* gv = g_vimg + (size_t)h * NTILE * V_IMG;

    // ---- prologue: async K0,V0; Q converted inline ----
#pragma unroll
    for (int i = 0; i < 9; ++i){
        int u = t + NT * i;
        cpa16(sb + SM_K + u*16, gk + u*16);      // 1152 units
    }
    CPA_COMMIT();                      // group: K0
#pragma unroll
    for (int i = 0; i < 10; ++i){
        int u = t + NT * i;
        cpa16(sb + SM_V + u*16, gv + u*16);      // 1280 units
    }
    CPA_COMMIT();                      // group: V0

    const float QSCALE = 0.08838834764831845f * 1.4426950408889634f;
    {
        const float* Qt = q + ((size_t)h * S_LEN + (size_t)qt * BM) * DH;
#pragma unroll
        for (int i = 0; i < 32; ++i){           // 128 rows * 32 combos
            int idx = t + NT * i;
            int row = idx >> 5, kc = idx & 31;
            int kk = kc >> 2, c = kc & 3;
            int d0 = 16*kk + 2*c;
            float2 v0 = *(const float2*)(Qt + row * DH + d0);
            float2 v1 = *(const float2*)(Qt + row * DH + d0 + 8);
            uint2 u = make_uint2(pkh(__float2half_rn(v0.x * QSCALE),
                                     __float2half_rn(v0.y * QSCALE)),
                                 pkh(__float2half_rn(v1.x * QSCALE),
                                     __float2half_rn(v1.y * QSCALE)));
            *(uint2*)(sm + SM_Q + row * RS_QK + kk * 32 + c * 8) = u;
        }
    }

    // two rowblocks per warp: rows 32w+r3(+8) and 32w+16+r3(+8)
    float o0[16][4], o1[16][4];
#pragma unroll
    for (int i = 0; i < 16; ++i){
        o0[i][0]=o0[i][1]=o0[i][2]=o0[i][3]=0.f;
        o1[i][0]=o1[i][1]=o1[i][2]=o1[i][3]=0.f;
    }
    float m0=-1e30f, m1=-1e30f, m2=-1e30f, m3=-1e30f;
    float l0=0.f, l1=0.f, l2=0.f, l3=0.f;

    const int r3 = l >> 2, cc = l & 3;
    const uint32_t qa    = SM_Q + (uint32_t)(32*w + r3) * RS_QK + cc*8;
    const uint32_t kfrag = SM_K + (uint32_t)r3 * RS_QK + cc*8;
    const uint32_t vfrag = SM_V + (uint32_t)r3 * RS_V + cc*8;

#pragma unroll 1
    for (int kt = 0; kt < nkt; ++kt){
        CPA_WAIT(1);                   // completes K(kt)
        __syncthreads();

        // ---- MMA1: S = Q K^T, both rowblocks share B fragments ----
        float c0[8][4], c1[8][4];
#pragma unroll
        for (int i = 0; i < 8; ++i){
            c0[i][0]=c0[i][1]=c0[i][2]=c0[i][3]=0.f;
            c1[i][0]=c1[i][1]=c1[i][2]=c1[i][3]=0.f;
        }
#pragma unroll
        for (int kk = 0; kk < 8; ++kk){
            uint2 A00 = *(const uint2*)(sm + qa + kk*32);
            uint2 A01 = *(const uint2*)(sm + qa + kk*32 +  8*RS_QK);
            uint2 A10 = *(const uint2*)(sm + qa + kk*32 + 16*RS_QK);
            uint2 A11 = *(const uint2*)(sm + qa + kk*32 + 24*RS_QK);
#pragma unroll
            for (int nt = 0; nt < 8; ++nt){
                uint2 B = *(const uint2*)(sm + kfrag + nt*(8*RS_QK) + kk*32);
                mma_f16(c0[nt], A00.x, A01.x, A00.y, A01.y, B.x, B.y);
                mma_f16(c1[nt], A10.x, A11.x, A10.y, A11.y, B.x, B.y);
            }
        }

        // ---- causal mask (last two k-tiles straddle the diagonal) ----
        if (kt >= nkt - 2){
            int gr = qt*BM + 32*w + r3;       // rowblock0 row; +8, +16, +24
            int cb = kt*BN + 2*cc;
#pragma unroll
            for (int nt = 0; nt < 8; ++nt){
                int gc = cb + 8*nt;
                if (gc   > gr)      c0[nt][0] = -1e30f;
                if (gc+1 > gr)      c0[nt][1] = -1e30f;
                if (gc   > gr+8)    c0[nt][2] = -1e30f;
                if (gc+1 > gr+8)    c0[nt][3] = -1e30f;
                if (gc   > gr+16)   c1[nt][0] = -1e30f;
                if (gc+1 > gr+16)   c1[nt][1] = -1e30f;
                if (gc   > gr+24)   c1[nt][2] = -1e30f;
                if (gc+1 > gr+24)   c1[nt][3] = -1e30f;
            }
        }

        __syncthreads();               // all warps done reading K(kt)
        if (kt + 1 < nkt){             // prefetch K(kt+1)
            const char* gk2 = gk + (size_t)(kt + 1) * K_IMG;
#pragma unroll
            for (int i = 0; i < 9; ++i){
                int u = t + NT * i;
                cpa16(sb + SM_K + u*16, gk2 + u*16);
            }
            CPA_COMMIT();
        }

        // ---- online softmax (log2 domain), 4 rows per thread ----
        float tm0=-1e30f, tm1=-1e30f, tm2=-1e30f, tm3=-1e30f;
#pragma unroll
        for (int nt = 0; nt < 8; ++nt){
            tm0 = fmaxf(tm0, fmaxf(c0[nt][0], c0[nt][1]));
            tm1 = fmaxf(tm1, fmaxf(c0[nt][2], c0[nt][3]));
            tm2 = fmaxf(tm2, fmaxf(c1[nt][0], c1[nt][1]));
            tm3 = fmaxf(tm3, fmaxf(c1[nt][2], c1[nt][3]));
        }
#pragma unroll
        for (int ofs = 1; ofs <= 2; ofs <<= 1){
            tm0 = fmaxf(tm0, __shfl_xor_sync(0xffffffffu, tm0, ofs));
            tm1 = fmaxf(tm1, __shfl_xor_sync(0xffffffffu, tm1, ofs));
            tm2 = fmaxf(tm2, __shfl_xor_sync(0xffffffffu, tm2, ofs));
            tm3 = fmaxf(tm3, __shfl_xor_sync(0xffffffffu, tm3, ofs));
        }
        float mn0 = fmaxf(m0, tm0), mn1 = fmaxf(m1, tm1);
        float mn2 = fmaxf(m2, tm2), mn3 = fmaxf(m3, tm3);
        float al0 = ex2f_(m0 - mn0), al1 = ex2f_(m1 - mn1);
        float al2 = ex2f_(m2 - mn2), al3 = ex2f_(m3 - mn3);
        m0 = mn0; m1 = mn1; m2 = mn2; m3 = mn3;

        uint32_t phi0[16], phi1[16];
        float rs0=0.f, rs1=0.f, rs2=0.f, rs3=0.f;
#pragma unroll
        for (int nt = 0; nt < 8; ++nt){
            float p0 = ex2f_(c0[nt][0]-mn0), p1 = ex2f_(c0[nt][1]-mn0);
            float p2 = ex2f_(c0[nt][2]-mn1), p3 = ex2f_(c0[nt][3]-mn1);
            float p4 = ex2f_(c1[nt][0]-mn2), p5 = ex2f_(c1[nt][1]-mn2);
            float p6 = ex2f_(c1[nt][2]-mn3), p7 = ex2f_(c1[nt][3]-mn3);
            rs0 += p0 + p1; rs1 += p2 + p3;
            rs2 += p4 + p5; rs3 += p6 + p7;
            int base = (nt >> 1)*4 + (nt & 1)*2;
            phi0[base]   = pkh(__float2half_rn(p0), __float2half_rn(p1));
            phi0[base+1] = pkh(__float2half_rn(p2), __float2half_rn(p3));
            phi1[base]   = pkh(__float2half_rn(p4), __float2half_rn(p5));
            phi1[base+1] = pkh(__float2half_rn(p6), __float2half_rn(p7));
        }
#pragma unroll
        for (int ofs = 1; ofs <= 2; ofs <<= 1){
            rs0 += __shfl_xor_sync(0xffffffffu, rs0, ofs);
            rs1 += __shfl_xor_sync(0xffffffffu, rs1, ofs);
            rs2 += __shfl_xor_sync(0xffffffffu, rs2, ofs);
            rs3 += __shfl_xor_sync(0xffffffffu, rs3, ofs);
        }
        l0 = l0*al0 + rs0; l1 = l1*al1 + rs1;
        l2 = l2*al2 + rs2; l3 = l3*al3 + rs3;

#pragma unroll
        for (int i = 0; i < 16; ++i){
            o0[i][0] *= al0; o0[i][1] *= al0; o0[i][2] *= al1; o0[i][3] *= al1;
            o1[i][0] *= al2; o1[i][1] *= al2; o1[i][2] *= al3; o1[i][3] *= al3;
        }

        // V(kt) must be complete (final iter has no trailing K group)
        if (kt + 1 < nkt){ CPA_WAIT(1); } else { CPA_WAIT(0); }
        __syncthreads();

        // ---- MMA2: O += P V, both rowblocks share V fragments ----
#pragma unroll
        for (int kkp = 0; kkp < 4; ++kkp){
            uint32_t pa0 = phi0[4*kkp], pa1 = phi0[4*kkp+1],
                     pa2 = phi0[4*kkp+2], pa3 = phi0[4*kkp+3];
            uint32_t pb0 = phi1[4*kkp], pb1 = phi1[4*kkp+1],
                     pb2 = phi1[4*kkp+2], pb3 = phi1[4*kkp+3];
#pragma unroll
            for (int nt2 = 0; nt2 < 16; ++nt2){
                uint2 B = *(const uint2*)(sm + vfrag + nt2*(8*RS_V) + kkp*32);
                mma_f16(o0[nt2], pa0,pa1,pa2,pa3, B.x, B.y);
                mma_f16(o1[nt2], pb0,pb1,pb2,pb3, B.x, B.y);
            }
        }

        __syncthreads();               // all warps done reading V(kt)
        if (kt + 1 < nkt){             // prefetch V(kt+1)
            const char* gv2 = gv + (size_t)(kt + 1) * V_IMG;
#pragma unroll
            for (int i = 0; i < 10; ++i){
                int u = t + NT * i;
                cpa16(sb + SM_V + u*16, gv2 + u*16);
            }
            CPA_COMMIT();
        }
    }

    // ---- epilogue ----
    float inv0 = 1.f/l0, inv1 = 1.f/l1, inv2 = 1.f/l2, inv3 = 1.f/l3;
    int r0 = qt*BM + 32*w + r3;
    float* po = out + ((size_t)h * S_LEN + r0) * DH + 2*cc;
#pragma unroll
    for (int nt2 = 0; nt2 < 16; ++nt2){
        *(float2*)(po + 8*nt2)          = make_float2(o0[nt2][0]*inv0, o0[nt2][1]*inv0);
        *(float2*)(po +  8*DH + 8*nt2)  = make_float2(o0[nt2][2]*inv1, o0[nt2][3]*inv1);
        *(float2*)(po + 16*DH + 8*nt2)  = make_float2(o1[nt2][0]*inv2, o1[nt2][1]*inv2);
        *(float2*)(po + 24*DH + 8*nt2)  = make_float2(o1[nt2][2]*inv3, o1[nt2][3]*inv3);
    }
    if (cc == 0){
        const float LN2 = 0.6931471805599453f;
        size_t s0 = ((size_t)h * S_LEN + r0) * 8;
        float mv[4] = {m0*LN2, m1*LN2, m2*LN2, m3*LN2};
        float lv[4] = {l0, l1, l2, l3};
#pragma unroll
        for (int rbl = 0; rbl < 4; ++rbl){
            size_t s = s0 + (size_t)rbl * 64;     // rows r0, r0+8, r0+16, r0+24
            float4 mq = make_float4(mv[rbl], mv[rbl], mv[rbl], mv[rbl]);
            float4 lq = make_float4(lv[rbl], lv[rbl], lv[rbl], lv[rbl]);
            *(float4*)(omax + s) = mq; *(float4*)(omax + s + 4) = mq;
            *(float4*)(osum + s) = lq; *(float4*)(osum + s + 4) = lq;
        }
    }
}

extern "C" void kernel_launch(void* const* d_in, const int* in_sizes, int n_in,
                              void* d_out, int out_size)
{
    const float* q = (const float*)d_in[0];
    const float* k = (const float*)d_in[1];
    const float* v = (const float*)d_in[2];

    float* out  = (float*)d_out;
    float* omax = out + (size_t)32 * 2048 * 128;
    float* osum = omax + (size_t)32 * 2048 * 8;

    dim3 pgrid(NTILE, NHEAD);
    fa_prep_kernel<<<pgrid, NT>>>(k, v);

    cudaFuncSetAttribute(fa_main_kernel,
                         cudaFuncAttributeMaxDynamicSharedMemorySize, SMEM_BYTES);
    dim3 grid(NQT, NHEAD);   // (128-row q-tiles, heads)
    fa_main_kernel<<<grid, NT, SMEM_BYTES>>>(q, out, omax, osum);
}

// round 13
// speedup vs baseline: 1.4428x; 1.4428x over previous
#include <cuda_runtime.h>
#include <cuda_fp16.h>
#include <cstdint>

// FlashAttentionScore B=2,N=16,S=2048,D=128 fp32 causal.
// prep: K,V -> PACKED fp16 fragment images (V transposed via smem staging).
// main: cp.async (packed src -> padded smem rows 288/160), mma.sync fp16 1-term.
// out layout: [out 32*2048*128][max x8][sum x8]

#define S_LEN 2048
#define DH    128
#define BM    64
#define BN    64
#define NT    128
#define NHEAD 32
#define NTILE 32

#define RS_QK 288           // smem row stride (≡8 mod 32 words: conflict-free)
#define RS_V  160
#define KG_IMG 16384        // packed gmem: 64 rows * 256B
#define VG_IMG 16384        // packed gmem: 128 rows * 128B

#define SM_Q  0             // 64*288 = 18432
#define SM_K  18432
#define SM_V  36864         // 128*160 = 20480
#define SMEM_BYTES 57344    // 3 CTAs/SM

__device__ __align__(16) char g_kimg[NHEAD * NTILE * KG_IMG];   // 16.8 MB
__device__ __align__(16) char g_vimg[NHEAD * NTILE * VG_IMG];   // 16.8 MB

__device__ __forceinline__ float ex2f_(float x){
    float r; asm("ex2.approx.ftz.f32 %0, %1;" : "=f"(r) : "f"(x)); return r;
}
__device__ __forceinline__ uint32_t pkh(__half a, __half b){
    return (uint32_t)__half_as_ushort(a) | ((uint32_t)__half_as_ushort(b) << 16);
}
__device__ __forceinline__ void mma_f16(float c[4],
        uint32_t a0, uint32_t a1, uint32_t a2, uint32_t a3,
        uint32_t b0, uint32_t b1){
    asm volatile(
        "mma.sync.aligned.m16n8k16.row.col.f32.f16.f16.f32 "
        "{%0,%1,%2,%3}, {%4,%5,%6,%7}, {%8,%9}, {%0,%1,%2,%3};"
        : "+f"(c[0]), "+f"(c[1]), "+f"(c[2]), "+f"(c[3])
        : "r"(a0), "r"(a1), "r"(a2), "r"(a3), "r"(b0), "r"(b1));
}
__device__ __forceinline__ uint32_t smem_u32(const void* p){
    uint32_t a;
    asm("{ .reg .u64 t; cvta.to.shared.u64 t, %1; cvt.u32.u64 %0, t; }" : "=r"(a) : "l"(p));
    return a;
}
__device__ __forceinline__ void cpa16(uint32_t s, const char* g){
    asm volatile("cp.async.cg.shared.global [%0], [%1], 16;" :: "r"(s), "l"(g));
}
#define CPA_COMMIT() asm volatile("cp.async.commit_group;" ::: "memory")
#define CPA_WAIT(n)  asm volatile("cp.async.wait_group %0;" :: "n"(n) : "memory")

// Fragment layout (packed gmem / padded smem): row*pitch + kk*32 + c*8
//   8B unit = [pair(8kk+c), pair(8kk+4+c)], pair w = k-elements {2w,2w+1}
//   Q/K: row = q/key (8 kk);  V: row = d (4 kk)

// ---------------- prep ----------------
__global__ void __launch_bounds__(NT)
fa_prep_kernel(const float* __restrict__ k, const float* __restrict__ v)
{
    __shared__ float sv[64 * 132];     // V tile staging (row=key, pad 132)
    const int t  = threadIdx.x;
    const int kt = blockIdx.x;
    const int h  = blockIdx.y;
    const int img = h * NTILE + kt;

    // ---- K tile -> packed fp16 image (contiguous 256B row writes) ----
    {
        const float* Kt = k + ((size_t)h * S_LEN + (size_t)kt * BN) * DH;
        char* kb = g_kimg + (size_t)img * KG_IMG;
#pragma unroll
        for (int i = 0; i < 16; ++i){
            int idx = t + NT * i;            // row*32 + kk*4 + c
            int row = idx >> 5, kc = idx & 31;
            int kk = kc >> 2, c = kc & 3;
            int d0 = 16*kk + 2*c;
            float2 v0 = *(const float2*)(Kt + row * DH + d0);
            float2 v1 = *(const float2*)(Kt + row * DH + d0 + 8);
            uint2 u = make_uint2(pkh(__float2half_rn(v0.x), __float2half_rn(v0.y)),
                                 pkh(__float2half_rn(v1.x), __float2half_rn(v1.y)));
            *(uint2*)(kb + row * 256 + kk * 32 + c * 8) = u;
        }
    }
    // ---- V tile: coalesced fp32 load -> smem -> coalesced transposed write ----
    {
        const float* Vt = v + ((size_t)h * S_LEN + (size_t)kt * BN) * DH;
#pragma unroll
        for (int i = 0; i < 64; ++i){
            int idx = t + NT * i;            // key*128 + d
            int key = idx >> 7, d = idx & 127;
            sv[key * 132 + d] = Vt[idx];
        }
        __syncthreads();
        char* vb = g_vimg + (size_t)img * VG_IMG;
        int j  = t & 15;                     // unit within 128B row (j = 4kk + c)
        int kk = j >> 2, c = j & 3;
        int k0 = 16*kk + 2*c;
#pragma unroll
        for (int p = 0; p < 16; ++p){
            int d = p * 8 + (t >> 4);
            float a  = sv[(k0    ) * 132 + d];
            float b  = sv[(k0 + 1) * 132 + d];
            float e  = sv[(k0 + 8) * 132 + d];
            float f  = sv[(k0 + 9) * 132 + d];
            *(uint2*)(vb + d * 128 + j * 8) =
                make_uint2(pkh(__float2half_rn(a), __float2half_rn(b)),
                           pkh(__float2half_rn(e), __float2half_rn(f)));
        }
    }
}

// ---------------- main ----------------
__global__ void __launch_bounds__(NT, 3)
fa_main_kernel(const float* __restrict__ q, float* __restrict__ out,
               float* __restrict__ omax, float* __restrict__ osum)
{
    extern __shared__ char sm[];
    const int t = threadIdx.x;
    const int l = t & 31;
    const int w = t >> 5;
    const int h = blockIdx.x;                    // head-major launch
    const int qt = NTILE - 1 - (int)blockIdx.y;  // all heads' big tiles first
    const int nkt = qt + 1;

    const uint32_t sb = smem_u32(sm);
    const char* gk = g_kimg + (size_t)h * NTILE * KG_IMG;
    const char* gv = g_vimg + (size_t)h * NTILE * VG_IMG;

    // ---- prologue: async K0,V0 (packed->padded); Q converted inline ----
#pragma unroll
    for (int i = 0; i < 8; ++i){
        int u = t + NT * i;                      // 1024 K units
        cpa16(sb + SM_K + (u >> 4) * RS_QK + (u & 15) * 16, gk + u*16);
    }
    CPA_COMMIT();                      // group: K0
#pragma unroll
    for (int i = 0; i < 8; ++i){
        int u = t + NT * i;                      // 1024 V units
        cpa16(sb + SM_V + (u >> 3) * RS_V + (u & 7) * 16, gv + u*16);
    }
    CPA_COMMIT();                      // group: V0

    const float QSCALE = 0.08838834764831845f * 1.4426950408889634f;
    {
        const float* Qt = q + ((size_t)h * S_LEN + (size_t)qt * BM) * DH;
#pragma unroll
        for (int i = 0; i < 16; ++i){
            int idx = t + NT * i;
            int row = idx >> 5, kc = idx & 31;
            int kk = kc >> 2, c = kc & 3;
            int d0 = 16*kk + 2*c;
            float2 v0 = *(const float2*)(Qt + row * DH + d0);
            float2 v1 = *(const float2*)(Qt + row * DH + d0 + 8);
            uint2 u = make_uint2(pkh(__float2half_rn(v0.x * QSCALE),
                                     __float2half_rn(v0.y * QSCALE)),
                                 pkh(__float2half_rn(v1.x * QSCALE),
                                     __float2half_rn(v1.y * QSCALE)));
            *(uint2*)(sm + SM_Q + row * RS_QK + kk * 32 + c * 8) = u;
        }
    }

    float o[16][4];
#pragma unroll
    for (int i = 0; i < 16; ++i){ o[i][0]=o[i][1]=o[i][2]=o[i][3]=0.f; }
    float m0=-1e30f, m1=-1e30f, l0=0.f, l1=0.f;

    const int r3 = l >> 2, cc = l & 3;
    const uint32_t qa    = SM_Q + (uint32_t)(16*w + r3) * RS_QK + cc*8;
    const uint32_t kfrag = SM_K + (uint32_t)r3 * RS_QK + cc*8;
    const uint32_t vfrag = SM_V + (uint32_t)r3 * RS_V + cc*8;

#pragma unroll 1
    for (int kt = 0; kt < nkt; ++kt){
        CPA_WAIT(1);                   // completes K(kt)
        __syncthreads();

        // ---- MMA1: S = Q K^T ----
        float c[8][4];
#pragma unroll
        for (int i = 0; i < 8; ++i){ c[i][0]=c[i][1]=c[i][2]=c[i][3]=0.f; }
#pragma unroll
        for (int kk = 0; kk < 8; ++kk){
            uint2 A0 = *(const uint2*)(sm + qa + kk*32);
            uint2 A1 = *(const uint2*)(sm + qa + kk*32 + 8*RS_QK);
#pragma unroll
            for (int nt = 0; nt < 8; ++nt){
                uint2 B = *(const uint2*)(sm + kfrag + nt*(8*RS_QK) + kk*32);
                mma_f16(c[nt], A0.x, A1.x, A0.y, A1.y, B.x, B.y);
            }
        }

        // ---- causal mask (diagonal tile only) ----
        if (kt == qt){
            int gr0 = qt*BM + 16*w + r3;
            int cb  = kt*BN + 2*cc;
#pragma unroll
            for (int nt = 0; nt < 8; ++nt){
                int gc = cb + 8*nt;
                if (gc   > gr0)   c[nt][0] = -1e30f;
                if (gc+1 > gr0)   c[nt][1] = -1e30f;
                if (gc   > gr0+8) c[nt][2] = -1e30f;
                if (gc+1 > gr0+8) c[nt][3] = -1e30f;
            }
        }

        __syncthreads();               // all warps done reading K(kt)
        if (kt + 1 < nkt){             // prefetch K(kt+1)
            const char* gk2 = gk + (size_t)(kt + 1) * KG_IMG;
#pragma unroll
            for (int i = 0; i < 8; ++i){
                int u = t + NT * i;
                cpa16(sb + SM_K + (u >> 4) * RS_QK + (u & 15) * 16, gk2 + u*16);
            }
            CPA_COMMIT();
        }

        // ---- online softmax (log2 domain) ----
        float tm0 = -1e30f, tm1 = -1e30f;
#pragma unroll
        for (int nt = 0; nt < 8; ++nt){
            tm0 = fmaxf(tm0, fmaxf(c[nt][0], c[nt][1]));
            tm1 = fmaxf(tm1, fmaxf(c[nt][2], c[nt][3]));
        }
        tm0 = fmaxf(tm0, __shfl_xor_sync(0xffffffffu, tm0, 1));
        tm0 = fmaxf(tm0, __shfl_xor_sync(0xffffffffu, tm0, 2));
        tm1 = fmaxf(tm1, __shfl_xor_sync(0xffffffffu, tm1, 1));
        tm1 = fmaxf(tm1, __shfl_xor_sync(0xffffffffu, tm1, 2));
        float mn0 = fmaxf(m0, tm0), mn1 = fmaxf(m1, tm1);
        float al0 = ex2f_(m0 - mn0), al1 = ex2f_(m1 - mn1);
        m0 = mn0; m1 = mn1;

        uint32_t phi[16];
        float rs0 = 0.f, rs1 = 0.f;
#pragma unroll
        for (int nt = 0; nt < 8; ++nt){
            float p0 = ex2f_(c[nt][0]-mn0), p1 = ex2f_(c[nt][1]-mn0);
            float p2 = ex2f_(c[nt][2]-mn1), p3 = ex2f_(c[nt][3]-mn1);
            rs0 += p0 + p1; rs1 += p2 + p3;
            int base = (nt >> 1)*4 + (nt & 1)*2;
            phi[base]   = pkh(__float2half_rn(p0), __float2half_rn(p1));
            phi[base+1] = pkh(__float2half_rn(p2), __float2half_rn(p3));
        }
        rs0 += __shfl_xor_sync(0xffffffffu, rs0, 1);
        rs0 += __shfl_xor_sync(0xffffffffu, rs0, 2);
        rs1 += __shfl_xor_sync(0xffffffffu, rs1, 1);
        rs1 += __shfl_xor_sync(0xffffffffu, rs1, 2);
        l0 = l0*al0 + rs0; l1 = l1*al1 + rs1;

#pragma unroll
        for (int i = 0; i < 16; ++i){
            o[i][0] *= al0; o[i][1] *= al0; o[i][2] *= al1; o[i][3] *= al1;
        }

        // V(kt) complete: mid-loop wait(1) (K(kt+1) pending); final wait(0)
        if (kt + 1 < nkt){ CPA_WAIT(1); } else { CPA_WAIT(0); }
        __syncthreads();

        // ---- MMA2: O += P V ----
#pragma unroll
        for (int kkp = 0; kkp < 4; ++kkp){
            uint32_t pa0 = phi[4*kkp], pa1 = phi[4*kkp+1],
                     pa2 = phi[4*kkp+2], pa3 = phi[4*kkp+3];
#pragma unroll
            for (int nt2 = 0; nt2 < 16; ++nt2){
                uint2 B = *(const uint2*)(sm + vfrag + nt2*(8*RS_V) + kkp*32);
                mma_f16(o[nt2], pa0,pa1,pa2,pa3, B.x, B.y);
            }
        }

        __syncthreads();               // all warps done reading V(kt)
        if (kt + 1 < nkt){             // prefetch V(kt+1)
            const char* gv2 = gv + (size_t)(kt + 1) * VG_IMG;
#pragma unroll
            for (int i = 0; i < 8; ++i){
                int u = t + NT * i;
                cpa16(sb + SM_V + (u >> 3) * RS_V + (u & 7) * 16, gv2 + u*16);
            }
            CPA_COMMIT();
        }
    }

    // ---- epilogue ----
    float inv0 = 1.f / l0, inv1 = 1.f / l1;
    int r0 = qt*BM + 16*w + r3;
    float* po = out + ((size_t)h * S_LEN + r0) * DH + 2*cc;
#pragma unroll
    for (int nt2 = 0; nt2 < 16; ++nt2){
        *(float2*)(po + 8*nt2)        = make_float2(o[nt2][0]*inv0, o[nt2][1]*inv0);
        *(float2*)(po + 8*DH + 8*nt2) = make_float2(o[nt2][2]*inv1, o[nt2][3]*inv1);
    }
    if (cc == 0){
        const float LN2 = 0.6931471805599453f;
        size_t s0 = ((size_t)h * S_LEN + r0) * 8;
        size_t s1 = s0 + 64;   // row + 8
        float mn0 = m0 * LN2, mn1 = m1 * LN2;
        float4 mv0 = make_float4(mn0, mn0, mn0, mn0);
        float4 mv1 = make_float4(mn1, mn1, mn1, mn1);
        float4 lv0 = make_float4(l0, l0, l0, l0);
        float4 lv1 = make_float4(l1, l1, l1, l1);
        *(float4*)(omax + s0) = mv0; *(float4*)(omax + s0 + 4) = mv0;
        *(float4*)(omax + s1) = mv1; *(float4*)(omax + s1 + 4) = mv1;
        *(float4*)(osum + s0) = lv0; *(float4*)(osum + s0 + 4) = lv0;
        *(float4*)(osum + s1) = lv1; *(float4*)(osum + s1 + 4) = lv1;
    }
}

extern "C" void kernel_launch(void* const* d_in, const int* in_sizes, int n_in,
                              void* d_out, int out_size)
{
    const float* q = (const float*)d_in[0];
    const float* k = (const float*)d_in[1];
    const float* v = (const float*)d_in[2];

    float* out  = (float*)d_out;
    float* omax = out + (size_t)32 * 2048 * 128;
    float* osum = omax + (size_t)32 * 2048 * 8;

    dim3 pgrid(NTILE, NHEAD);
    fa_prep_kernel<<<pgrid, NT>>>(k, v);

    cudaFuncSetAttribute(fa_main_kernel,
                         cudaFuncAttributeMaxDynamicSharedMemorySize, SMEM_BYTES);
    dim3 grid(NHEAD, NTILE);   // head-major: all heads' heavy tiles first
    fa_main_kernel<<<grid, NT, SMEM_BYTES>>>(q, out, omax, osum);
}